// round 13
// baseline (speedup 1.0000x reference)
#include <cuda_runtime.h>
#include <cstdint>

// ---------------- problem constants ----------------
#define BB   32
#define SS   512
#define GG   512
#define DD   768
#define GDD  16
#define KX   816           // D + 3*GD
#define VV   30522
#define M_TOT (BB*SS)      // 16384
#define LN_EPS 1e-12f

// ---------------- device scratch ----------------
// g_A / g_wp hold tf32-rounded operands in PERMUTED-k layout: within each
// 16-float k-block, position 4t+i holds k = t + 4i  (t,i in 0..3).
// Applied identically to A and B the GEMM k-sum is unchanged; one float4
// per row then carries a thread's fragments for BOTH k-substeps -> LDS.128.
__device__ float g_colpart[3][BB][4][GG];    // partial column sums of adj
__device__ float g_gpart[3][BB][4][DD];      // partial graph vectors
__device__ float g_graph[BB][3*GDD];         // concat(relu(g@W^T+b))
__device__ float g_A[(size_t)M_TOT * DD];    // tf32(word_emb[id]+pos_emb[s]), permuted
__device__ float g_wp[DD * DD];              // tf32(Wp[:, :768]), permuted

__device__ __forceinline__ float tf32f(float x)
{
    uint32_t h;
    asm("cvt.rna.tf32.f32 %0, %1;" : "=r"(h) : "f"(x));
    return __uint_as_float(h);
}
__device__ __forceinline__ uint32_t smem_u32(const void* p) {
    uint32_t a;
    asm("{ .reg .u64 t; cvta.to.shared.u64 t, %1; cvt.u32.u64 %0, t; }"
        : "=r"(a) : "l"(p));
    return a;
}
__device__ __forceinline__ void cpa16(uint32_t dst, const float* src) {
    asm volatile("cp.async.cg.shared.global [%0], [%1], 16;"
                 :: "r"(dst), "l"(src));
}
__device__ __forceinline__ void mma_tf32(float* c, const uint32_t* a, const uint32_t* b)
{
    asm("mma.sync.aligned.m16n8k8.row.col.f32.tf32.tf32.f32 "
        "{%0,%1,%2,%3}, {%4,%5,%6,%7}, {%8,%9}, {%0,%1,%2,%3};"
        : "+f"(c[0]), "+f"(c[1]), "+f"(c[2]), "+f"(c[3])
        : "r"(a[0]), "r"(a[1]), "r"(a[2]), "r"(a[3]), "r"(b[0]), "r"(b[1]));
}

// =====================================================================
// pack: A[m] = tf32(word_emb[id[m]] + pos_emb[m&511]) permuted-k(16)
// block 192 = 4 rows x 48 groups; grid M_TOT/4
// =====================================================================
__global__ __launch_bounds__(192)
void pack_kernel(const int* __restrict__ ids,
                 const float* __restrict__ we,
                 const float* __restrict__ pe)
{
    const int t = threadIdx.x;
    const int m = blockIdx.x * 4 + (t / 48);
    const int grp = t % 48;                       // 16-float k-block
    const int id = __ldg(&ids[m]);
    const float4* ws = (const float4*)(we + (size_t)id * DD) + grp * 4;
    const float4* ps = (const float4*)(pe + (size_t)(m & (SS - 1)) * DD) + grp * 4;
    float4 a = ws[0], b = ws[1], c = ws[2], d = ws[3];
    float4 pa = ps[0], pb = ps[1], pc = ps[2], pd = ps[3];
    a.x += pa.x; a.y += pa.y; a.z += pa.z; a.w += pa.w;
    b.x += pb.x; b.y += pb.y; b.z += pb.z; b.w += pb.w;
    c.x += pc.x; c.y += pc.y; c.z += pc.z; c.w += pc.w;
    d.x += pd.x; d.y += pd.y; d.z += pd.z; d.w += pd.w;
    float4 o0, o1, o2, o3;   // pos 4t+i <- k=t+4i
    o0.x = tf32f(a.x); o0.y = tf32f(b.x); o0.z = tf32f(c.x); o0.w = tf32f(d.x);
    o1.x = tf32f(a.y); o1.y = tf32f(b.y); o1.z = tf32f(c.y); o1.w = tf32f(d.y);
    o2.x = tf32f(a.z); o2.y = tf32f(b.z); o2.z = tf32f(c.z); o2.w = tf32f(d.z);
    o3.x = tf32f(a.w); o3.y = tf32f(b.w); o3.z = tf32f(c.w); o3.w = tf32f(d.w);
    float4* dst = (float4*)(g_A + (size_t)m * DD) + grp * 4;
    dst[0] = o0; dst[1] = o1; dst[2] = o2; dst[3] = o3;
}

// cvt Wp[:, :768] -> g_wp permuted-k(16); block 192 = 4 rows x 48; grid DD/4
__global__ __launch_bounds__(192)
void cvt_wp_kernel(const float* __restrict__ Wp)
{
    const int t = threadIdx.x;
    const int row = blockIdx.x * 4 + (t / 48);
    const int grp = t % 48;
    const float4* src = (const float4*)(Wp + (size_t)row * KX) + grp * 4;
    float4 a = src[0], b = src[1], c = src[2], d = src[3];
    float4 o0, o1, o2, o3;
    o0.x = tf32f(a.x); o0.y = tf32f(b.x); o0.z = tf32f(c.x); o0.w = tf32f(d.x);
    o1.x = tf32f(a.y); o1.y = tf32f(b.y); o1.z = tf32f(c.y); o1.w = tf32f(d.y);
    o2.x = tf32f(a.z); o2.y = tf32f(b.z); o2.z = tf32f(c.z); o2.w = tf32f(d.z);
    o3.x = tf32f(a.w); o3.y = tf32f(b.w); o3.z = tf32f(c.w); o3.w = tf32f(d.w);
    float4* dst = (float4*)(g_wp + (size_t)row * DD) + grp * 4;
    dst[0] = o0; dst[1] = o1; dst[2] = o2; dst[3] = o3;
}

// =====================================================================
// partial column sums of adj; grid (B, 3, 4), block 256
// =====================================================================
__global__ __launch_bounds__(256)
void colsum_kernel(const float* __restrict__ a0,
                   const float* __restrict__ a1,
                   const float* __restrict__ a2)
{
    int b = blockIdx.x, gi = blockIdx.y, c = blockIdx.z;
    const float* adj = (gi == 0 ? a0 : (gi == 1 ? a1 : a2))
                       + (size_t)b * GG * GG + (size_t)c * 128 * GG;
    for (int h = threadIdx.x; h < GG; h += blockDim.x) {
        float acc = 0.f;
        #pragma unroll 8
        for (int g = 0; g < 128; ++g)
            acc += adj[(size_t)g * GG + h];
        g_colpart[gi][b][c][h] = acc;
    }
}

// =====================================================================
// partial g[b,d] over a 128-node chunk; grid (B,3,4), block 768
// =====================================================================
__global__ __launch_bounds__(768)
void gvec_part_kernel(const float* __restrict__ word_emb,
                      const int* __restrict__ gv0, const int* __restrict__ gv1,
                      const int* __restrict__ gv2)
{
    int b = blockIdx.x, gi = blockIdx.y, c = blockIdx.z;
    const int* gv = (gi == 0 ? gv0 : (gi == 1 ? gv1 : gv2));

    __shared__ float ws[128];
    __shared__ int   ids[128];
    int t = threadIdx.x;
    if (t < 128) {
        int h = c * 128 + t;
        float s = g_colpart[gi][b][0][h] + g_colpart[gi][b][1][h]
                + g_colpart[gi][b][2][h] + g_colpart[gi][b][3][h];
        ws[t]  = s * (1.0f / GG);
        ids[t] = gv[b * GG + h];
    }
    __syncthreads();

    float acc = 0.f;
    #pragma unroll 8
    for (int h = 0; h < 128; ++h)
        acc += ws[h] * __ldg(&word_emb[(size_t)ids[h] * DD + t]);
    g_gpart[gi][b][c][t] = acc;
}

// =====================================================================
// reduce partials + fc + relu; grid (B,3), block 768
// =====================================================================
__global__ __launch_bounds__(768)
void gvec_fc_kernel(const float* __restrict__ W0, const float* __restrict__ W1,
                    const float* __restrict__ W2,
                    const float* __restrict__ c0, const float* __restrict__ c1,
                    const float* __restrict__ c2)
{
    int b = blockIdx.x, gi = blockIdx.y;
    const float* W    = (gi == 0 ? W0 : (gi == 1 ? W1 : W2));
    const float* bias = (gi == 0 ? c0 : (gi == 1 ? c1 : c2));

    __shared__ float gbuf[DD];
    int t = threadIdx.x;
    gbuf[t] = g_gpart[gi][b][0][t] + g_gpart[gi][b][1][t]
            + g_gpart[gi][b][2][t] + g_gpart[gi][b][3][t];
    __syncthreads();

    int w = t >> 5, lane = t & 31;
    if (w < GDD) {
        float s = 0.f;
        #pragma unroll
        for (int d = lane; d < DD; d += 32)
            s += gbuf[d] * W[w * DD + d];
        #pragma unroll
        for (int o = 16; o; o >>= 1)
            s += __shfl_xor_sync(0xffffffffu, s, o);
        if (lane == 0)
            g_graph[b][gi * GDD + w] = fmaxf(s + bias[w], 0.f);
    }
}

// =====================================================================
// Main GEMM: cp.async 4-stage pipeline + TF32 mma.sync, permuted-k LDS.128
//   C[m,n] = g_A[m] @ g_wp[n]^T + gpn[n]
// BM=BN=128, BK=16, 8 warps (64x32 warp tiles), smem dense [row][16]
// =====================================================================
#define BM 128
#define BN 128
#define BK 16
#define NT_TILES (DD / BK)     // 48
#define STAGES 4
#define ROWW   16              // dense; LDS.128 at 4*tg is conflict-free
#define HALF_W (128 * ROWW)             // 2048 words (A part)
#define STAGE_W (2 * HALF_W)            // 4096 words per stage
#define STAGE_B (STAGE_W * 4)           // 16384 bytes
#define HALF_B  (HALF_W * 4)            // 8192 bytes
#define GEMM_SMEM (STAGES * STAGE_B)    // 65536 bytes

__global__ __launch_bounds__(256, 2)
void gemm_async_kernel(const float* __restrict__ Wp,
                       const float* __restrict__ b_proj,
                       float*       __restrict__ out)
{
    extern __shared__ float smf[];
    __shared__ float grs[3 * GDD];
    __shared__ float gpn[BN];

    const int tid = threadIdx.x;
    const int m0  = blockIdx.y * BM;
    const int n0  = blockIdx.x * BN;
    const int bidx = blockIdx.y >> 2;

    const int warpId = tid >> 5;
    const int lane   = tid & 31;
    const int mW     = (warpId & 1) * 64;
    const int nW     = (warpId >> 1) * 32;
    const int g      = lane >> 2;
    const int tg     = lane & 3;

    // ---- loader mapping: one row + two 16B cp.async per operand ----
    const int arow = tid >> 1;            // 0..127
    const int koff = (tid & 1) * 8;       // word offset 0 or 8
    const float* srcA = g_A + (size_t)(m0 + arow) * DD + koff;
    const float* srcB = g_wp + (size_t)(n0 + arow) * DD + koff;

    const uint32_t sb = smem_u32(smf);
    const uint32_t dA = sb + (uint32_t)(arow * ROWW + koff) * 4;
    const uint32_t dB = dA + HALF_B;

    // ---- gpn staging ----
    if (tid < 3 * GDD) grs[tid] = g_graph[bidx][tid];
    __syncthreads();
    if (tid < BN) {
        const float* wrow = Wp + (size_t)(n0 + tid) * KX + DD;
        float a = b_proj[n0 + tid];
        #pragma unroll
        for (int j = 0; j < 3 * GDD; ++j)
            a += grs[j] * wrow[j];
        gpn[tid] = a;
    }

    float acc[4][4][4];
    #pragma unroll
    for (int mt = 0; mt < 4; ++mt)
        #pragma unroll
        for (int nt = 0; nt < 4; ++nt)
            #pragma unroll
            for (int r = 0; r < 4; ++r) acc[mt][nt][r] = 0.f;

    // ---- prefetch first STAGES-1 tiles ----
    #pragma unroll
    for (int s = 0; s < STAGES - 1; ++s) {
        const int k0 = s * BK;
        const uint32_t so = (uint32_t)s * STAGE_B;
        cpa16(dA + so,      srcA + k0);
        cpa16(dA + so + 16, srcA + k0 + 4);
        cpa16(dB + so,      srcB + k0);
        cpa16(dB + so + 16, srcB + k0 + 4);
        asm volatile("cp.async.commit_group;");
    }

    for (int t = 0; t < NT_TILES; ++t) {
        asm volatile("cp.async.wait_group %0;" :: "n"(STAGES - 2));
        __syncthreads();

        if (t + STAGES - 1 < NT_TILES) {
            const int tp = t + STAGES - 1;
            const int k0 = tp * BK;
            const uint32_t so = (uint32_t)(tp & (STAGES - 1)) * STAGE_B;
            cpa16(dA + so,      srcA + k0);
            cpa16(dA + so + 16, srcA + k0 + 4);
            cpa16(dB + so,      srcB + k0);
            cpa16(dB + so + 16, srcB + k0 + 4);
        }
        asm volatile("cp.async.commit_group;");

        const float* As_s = smf + (t & (STAGES - 1)) * STAGE_W;
        const float* Bs_s = As_s + HALF_W;

        // one LDS.128 per row carries fragments for BOTH k-substeps
        float4 bf[4];
        #pragma unroll
        for (int nt = 0; nt < 4; ++nt)
            bf[nt] = *(const float4*)&Bs_s[(nW + nt * 8 + g) * ROWW + 4 * tg];
        #pragma unroll
        for (int mt = 0; mt < 4; ++mt) {
            const int m = mW + mt * 16 + g;
            float4 alo = *(const float4*)&As_s[m * ROWW + 4 * tg];
            float4 ahi = *(const float4*)&As_s[(m + 8) * ROWW + 4 * tg];
            uint32_t af0[4], af1[4];
            af0[0] = __float_as_uint(alo.x); af0[1] = __float_as_uint(ahi.x);
            af0[2] = __float_as_uint(alo.y); af0[3] = __float_as_uint(ahi.y);
            af1[0] = __float_as_uint(alo.z); af1[1] = __float_as_uint(ahi.z);
            af1[2] = __float_as_uint(alo.w); af1[3] = __float_as_uint(ahi.w);
            #pragma unroll
            for (int nt = 0; nt < 4; ++nt) {
                uint32_t b0[2], b1[2];
                b0[0] = __float_as_uint(bf[nt].x); b0[1] = __float_as_uint(bf[nt].y);
                b1[0] = __float_as_uint(bf[nt].z); b1[1] = __float_as_uint(bf[nt].w);
                mma_tf32(acc[mt][nt], af0, b0);
                mma_tf32(acc[mt][nt], af1, b1);
            }
        }
    }
    asm volatile("cp.async.wait_group 0;");

    // ---- epilogue: + gpn, write out ----
    #pragma unroll
    for (int mt = 0; mt < 4; ++mt) {
        const int mBase = m0 + mW + mt * 16 + g;
        #pragma unroll
        for (int nt = 0; nt < 4; ++nt) {
            const int nl = nW + nt * 8 + tg * 2;
            float2 r0, r1;
            r0.x = acc[mt][nt][0] + gpn[nl];
            r0.y = acc[mt][nt][1] + gpn[nl + 1];
            r1.x = acc[mt][nt][2] + gpn[nl];
            r1.y = acc[mt][nt][3] + gpn[nl + 1];
            *(float2*)(out + (size_t)mBase * DD + n0 + nl)       = r0;
            *(float2*)(out + (size_t)(mBase + 8) * DD + n0 + nl) = r1;
        }
    }
}

// =====================================================================
// LayerNorm over last dim (768); block 192, one float4 per thread
// =====================================================================
__global__ __launch_bounds__(192)
void ln_kernel(float* __restrict__ y,
               const float* __restrict__ gamma,
               const float* __restrict__ beta)
{
    const int m = blockIdx.x;
    float4* row = (float4*)(y + (size_t)m * DD);
    const int t = threadIdx.x;

    float4 v = row[t];
    float s  = v.x + v.y + v.z + v.w;
    float s2 = v.x * v.x + v.y * v.y + v.z * v.z + v.w * v.w;
    #pragma unroll
    for (int o = 16; o; o >>= 1) {
        s  += __shfl_xor_sync(0xffffffffu, s,  o);
        s2 += __shfl_xor_sync(0xffffffffu, s2, o);
    }
    __shared__ float red[2][6];
    const int w = t >> 5, lane = t & 31;
    if (lane == 0) { red[0][w] = s; red[1][w] = s2; }
    __syncthreads();
    s = 0.f; s2 = 0.f;
    #pragma unroll
    for (int i = 0; i < 6; ++i) { s += red[0][i]; s2 += red[1][i]; }

    const float mean = s * (1.0f / DD);
    float var = s2 * (1.0f / DD) - mean * mean;
    var = fmaxf(var, 0.f);
    const float rstd = rsqrtf(var + LN_EPS);

    float4 ga = ((const float4*)gamma)[t];
    float4 be = ((const float4*)beta)[t];
    float4 o;
    o.x = (v.x - mean) * rstd * ga.x + be.x;
    o.y = (v.y - mean) * rstd * ga.y + be.y;
    o.z = (v.z - mean) * rstd * ga.z + be.z;
    o.w = (v.w - mean) * rstd * ga.w + be.w;
    row[t] = o;
}

// =====================================================================
// launch — fork/join: operand prep overlaps the graph chain
// =====================================================================
extern "C" void kernel_launch(void* const* d_in, const int* in_sizes, int n_in,
                              void* d_out, int out_size)
{
    const int*   input_ids = (const int*)  d_in[0];
    const float* adj_cooc  = (const float*)d_in[1];
    const int*   gv_cooc   = (const int*)  d_in[2];
    const float* adj_het   = (const float*)d_in[3];
    const int*   gv_het    = (const int*)  d_in[4];
    const float* adj_isg   = (const float*)d_in[5];
    const int*   gv_isg    = (const int*)  d_in[6];
    const float* word_emb  = (const float*)d_in[7];
    const float* pos_emb   = (const float*)d_in[8];
    const float* W_cooc    = (const float*)d_in[9];
    const float* b_cooc    = (const float*)d_in[10];
    const float* W_het     = (const float*)d_in[11];
    const float* b_het     = (const float*)d_in[12];
    const float* W_isg     = (const float*)d_in[13];
    const float* b_isg     = (const float*)d_in[14];
    const float* W_proj    = (const float*)d_in[15];
    const float* b_proj    = (const float*)d_in[16];
    const float* ln_gamma  = (const float*)d_in[17];
    const float* ln_beta   = (const float*)d_in[18];
    float* out = (float*)d_out;

    cudaFuncSetAttribute(gemm_async_kernel,
                         cudaFuncAttributeMaxDynamicSharedMemorySize, GEMM_SMEM);

    // fork a side stream for operand prep (captured via event fork/join)
    cudaStream_t s1;
    cudaStreamCreateWithFlags(&s1, cudaStreamNonBlocking);
    cudaEvent_t e0, e1;
    cudaEventCreateWithFlags(&e0, cudaEventDisableTiming);
    cudaEventCreateWithFlags(&e1, cudaEventDisableTiming);

    cudaEventRecord(e0, 0);
    cudaStreamWaitEvent(s1, e0, 0);
    pack_kernel<<<M_TOT / 4, 192, 0, s1>>>(input_ids, word_emb, pos_emb);
    cvt_wp_kernel<<<DD / 4, 192, 0, s1>>>(W_proj);
    cudaEventRecord(e1, s1);

    // graph chain on the main stream (concurrent with pack/cvt)
    colsum_kernel<<<dim3(BB, 3, 4), 256>>>(adj_cooc, adj_het, adj_isg);
    gvec_part_kernel<<<dim3(BB, 3, 4), 768>>>(word_emb, gv_cooc, gv_het, gv_isg);
    gvec_fc_kernel<<<dim3(BB, 3), 768>>>(W_cooc, W_het, W_isg,
                                         b_cooc, b_het, b_isg);

    // join, then main GEMM + LN
    cudaStreamWaitEvent(0, e1, 0);
    gemm_async_kernel<<<dim3(DD / BN, M_TOT / BM), 256, GEMM_SMEM>>>(
        W_proj, b_proj, out);
    ln_kernel<<<M_TOT, 192>>>(out, ln_gamma, ln_beta);

    // NOTE: s1/e0/e1 are intentionally NOT destroyed here — destroying a
    // stream/event that participates in an active capture invalidates it.
    // kernel_launch is invoked only a handful of times (correctness +
    // capture), so the host-side leak is bounded and device-safe.
}

// round 14
// speedup vs baseline: 1.1336x; 1.1336x over previous
#include <cuda_runtime.h>
#include <cstdint>

// ---------------- problem constants ----------------
#define BB   32
#define SS   512
#define GG   512
#define DD   768
#define GDD  16
#define KX   816           // D + 3*GD
#define VV   30522
#define M_TOT (BB*SS)      // 16384
#define LN_EPS 1e-12f

// ---------------- device scratch ----------------
// g_A / g_wp: tf32-rounded operands, PERMUTED-k: in each 8-float k-group,
// position 2j holds k=j, position 2j+1 holds k=j+4 (fragment pairs -> LDS.64).
__device__ float g_colpart[3][BB][4][GG];    // partial column sums of adj
__device__ float g_gpart[3][BB][4][DD];      // partial graph vectors
__device__ float g_graph[BB][3*GDD];         // concat(relu(g@W^T+b))
__device__ float g_gproj[BB][DD];            // b_proj + graph part of projection
__device__ float g_A[(size_t)M_TOT * DD];    // tf32(word_emb[id]+pos_emb[s]), permuted
__device__ float g_wp[DD * DD];              // tf32(Wp[:, :768]), permuted

__device__ __forceinline__ float tf32f(float x)
{
    uint32_t h;
    asm("cvt.rna.tf32.f32 %0, %1;" : "=r"(h) : "f"(x));
    return __uint_as_float(h);
}
__device__ __forceinline__ uint32_t smem_u32(const void* p) {
    uint32_t a;
    asm("{ .reg .u64 t; cvta.to.shared.u64 t, %1; cvt.u32.u64 %0, t; }"
        : "=r"(a) : "l"(p));
    return a;
}
__device__ __forceinline__ void cpa16(uint32_t dst, const float* src) {
    asm volatile("cp.async.cg.shared.global [%0], [%1], 16;"
                 :: "r"(dst), "l"(src));
}
__device__ __forceinline__ void mma_tf32(float* c, const uint32_t* a, const uint32_t* b)
{
    asm("mma.sync.aligned.m16n8k8.row.col.f32.tf32.tf32.f32 "
        "{%0,%1,%2,%3}, {%4,%5,%6,%7}, {%8,%9}, {%0,%1,%2,%3};"
        : "+f"(c[0]), "+f"(c[1]), "+f"(c[2]), "+f"(c[3])
        : "r"(a[0]), "r"(a[1]), "r"(a[2]), "r"(a[3]), "r"(b[0]), "r"(b[1]));
}

// =====================================================================
// pack: A[m] = tf32(word_emb[id[m]] + pos_emb[m&511]) permuted-k(8)
// block 384 = 4 rows x 96 groups; grid M_TOT/4
// =====================================================================
__global__ __launch_bounds__(384)
void pack_kernel(const int* __restrict__ ids,
                 const float* __restrict__ we,
                 const float* __restrict__ pe)
{
    const int t = threadIdx.x;
    const int m = blockIdx.x * 4 + (t / 96);
    const int grp = t % 96;                       // 8-float k-group
    const int id = __ldg(&ids[m]);
    const float4* ws = (const float4*)(we + (size_t)id * DD) + grp * 2;
    const float4* ps = (const float4*)(pe + (size_t)(m & (SS - 1)) * DD) + grp * 2;
    float4 wa = ws[0], wb = ws[1], pa = ps[0], pb = ps[1];
    float a0 = wa.x + pa.x, a1 = wa.y + pa.y, a2 = wa.z + pa.z, a3 = wa.w + pa.w;
    float b0 = wb.x + pb.x, b1 = wb.y + pb.y, b2 = wb.z + pb.z, b3 = wb.w + pb.w;
    float4 o0, o1;   // permute: (k0,k4,k1,k5), (k2,k6,k3,k7)
    o0.x = tf32f(a0); o0.y = tf32f(b0); o0.z = tf32f(a1); o0.w = tf32f(b1);
    o1.x = tf32f(a2); o1.y = tf32f(b2); o1.z = tf32f(a3); o1.w = tf32f(b3);
    float4* dst = (float4*)(g_A + (size_t)m * DD) + grp * 2;
    dst[0] = o0; dst[1] = o1;
}

// cvt Wp[:, :768] -> g_wp permuted-k(8); block 384 = 4 rows x 96; grid DD/4
__global__ __launch_bounds__(384)
void cvt_wp_kernel(const float* __restrict__ Wp)
{
    const int t = threadIdx.x;
    const int row = blockIdx.x * 4 + (t / 96);
    const int grp = t % 96;
    const float4* src = (const float4*)(Wp + (size_t)row * KX) + grp * 2;
    float4 a = src[0], b = src[1];
    float4 o0, o1;
    o0.x = tf32f(a.x); o0.y = tf32f(b.x); o0.z = tf32f(a.y); o0.w = tf32f(b.y);
    o1.x = tf32f(a.z); o1.y = tf32f(b.z); o1.z = tf32f(a.w); o1.w = tf32f(b.w);
    float4* dst = (float4*)(g_wp + (size_t)row * DD) + grp * 2;
    dst[0] = o0; dst[1] = o1;
}

// =====================================================================
// partial column sums of adj; grid (B, 3, 4), block 256
// =====================================================================
__global__ __launch_bounds__(256)
void colsum_kernel(const float* __restrict__ a0,
                   const float* __restrict__ a1,
                   const float* __restrict__ a2)
{
    int b = blockIdx.x, gi = blockIdx.y, c = blockIdx.z;
    const float* adj = (gi == 0 ? a0 : (gi == 1 ? a1 : a2))
                       + (size_t)b * GG * GG + (size_t)c * 128 * GG;
    for (int h = threadIdx.x; h < GG; h += blockDim.x) {
        float acc = 0.f;
        #pragma unroll 8
        for (int g = 0; g < 128; ++g)
            acc += adj[(size_t)g * GG + h];
        g_colpart[gi][b][c][h] = acc;
    }
}

// =====================================================================
// partial g[b,d] over a 128-node chunk; grid (B,3,4), block 768
// =====================================================================
__global__ __launch_bounds__(768)
void gvec_part_kernel(const float* __restrict__ word_emb,
                      const int* __restrict__ gv0, const int* __restrict__ gv1,
                      const int* __restrict__ gv2)
{
    int b = blockIdx.x, gi = blockIdx.y, c = blockIdx.z;
    const int* gv = (gi == 0 ? gv0 : (gi == 1 ? gv1 : gv2));

    __shared__ float ws[128];
    __shared__ int   ids[128];
    int t = threadIdx.x;
    if (t < 128) {
        int h = c * 128 + t;
        float s = g_colpart[gi][b][0][h] + g_colpart[gi][b][1][h]
                + g_colpart[gi][b][2][h] + g_colpart[gi][b][3][h];
        ws[t]  = s * (1.0f / GG);
        ids[t] = gv[b * GG + h];
    }
    __syncthreads();

    float acc = 0.f;
    #pragma unroll 8
    for (int h = 0; h < 128; ++h)
        acc += ws[h] * __ldg(&word_emb[(size_t)ids[h] * DD + t]);
    g_gpart[gi][b][c][t] = acc;
}

// =====================================================================
// reduce partials + fc + relu; grid (B,3), block 768
// =====================================================================
__global__ __launch_bounds__(768)
void gvec_fc_kernel(const float* __restrict__ W0, const float* __restrict__ W1,
                    const float* __restrict__ W2,
                    const float* __restrict__ c0, const float* __restrict__ c1,
                    const float* __restrict__ c2)
{
    int b = blockIdx.x, gi = blockIdx.y;
    const float* W    = (gi == 0 ? W0 : (gi == 1 ? W1 : W2));
    const float* bias = (gi == 0 ? c0 : (gi == 1 ? c1 : c2));

    __shared__ float gbuf[DD];
    int t = threadIdx.x;
    gbuf[t] = g_gpart[gi][b][0][t] + g_gpart[gi][b][1][t]
            + g_gpart[gi][b][2][t] + g_gpart[gi][b][3][t];
    __syncthreads();

    int w = t >> 5, lane = t & 31;
    if (w < GDD) {
        float s = 0.f;
        #pragma unroll
        for (int d = lane; d < DD; d += 32)
            s += gbuf[d] * W[w * DD + d];
        #pragma unroll
        for (int o = 16; o; o >>= 1)
            s += __shfl_xor_sync(0xffffffffu, s, o);
        if (lane == 0)
            g_graph[b][gi * GDD + w] = fmaxf(s + bias[w], 0.f);
    }
}

// =====================================================================
// gproj[b,d] = b_proj[d] + sum_j graph[b,j] * Wp[d, 768+j]; grid B, blk 768
// =====================================================================
__global__ __launch_bounds__(768)
void gproj_kernel(const float* __restrict__ Wp, const float* __restrict__ bp)
{
    int b = blockIdx.x, d = threadIdx.x;
    __shared__ float gr[3 * GDD];
    if (d < 3 * GDD) gr[d] = g_graph[b][d];
    __syncthreads();
    float acc = bp[d];
    #pragma unroll
    for (int j = 0; j < 3 * GDD; ++j)
        acc += gr[j] * __ldg(&Wp[(size_t)d * KX + DD + j]);
    g_gproj[b][d] = acc;
}

// =====================================================================
// Main GEMM: cp.async 4-stage pipeline + TF32 mma.sync, permuted-k LDS.64
//   out[m,n] = g_A[m] @ g_wp[n]^T          (PURE matmul; +gproj moved to LN)
// BM=BN=128, BK=16, 8 warps (64x32 warp tiles), smem [row][24]
// =====================================================================
#define BM 128
#define BN 128
#define BK 16
#define NT_TILES (DD / BK)     // 48
#define STAGES 4
#define ROWW   24              // 16 data + 8 pad words (conflict-free LDS.64)
#define HALF_W (128 * ROWW)             // 3072 words (A part)
#define STAGE_W (2 * HALF_W)            // 6144 words per stage
#define STAGE_B (STAGE_W * 4)           // 24576 bytes
#define HALF_B  (HALF_W * 4)            // 12288 bytes
#define GEMM_SMEM (STAGES * STAGE_B)    // 98304 bytes

__global__ __launch_bounds__(256, 2)
void gemm_async_kernel(float* __restrict__ out)
{
    extern __shared__ float smf[];

    const int tid = threadIdx.x;
    const int m0  = blockIdx.y * BM;
    const int n0  = blockIdx.x * BN;

    const int warpId = tid >> 5;
    const int lane   = tid & 31;
    const int mW     = (warpId & 1) * 64;
    const int nW     = (warpId >> 1) * 32;
    const int g      = lane >> 2;
    const int tg     = lane & 3;

    // ---- loader mapping: one row + two 16B cp.async per operand ----
    const int arow = tid >> 1;            // 0..127
    const int koff = (tid & 1) * 8;       // word offset 0 or 8
    const float* srcA = g_A + (size_t)(m0 + arow) * DD + koff;
    const float* srcB = g_wp + (size_t)(n0 + arow) * DD + koff;

    const uint32_t sb = smem_u32(smf);
    const uint32_t dA = sb + (uint32_t)(arow * ROWW + koff) * 4;
    const uint32_t dB = dA + HALF_B;

    float acc[4][4][4];
    #pragma unroll
    for (int mt = 0; mt < 4; ++mt)
        #pragma unroll
        for (int nt = 0; nt < 4; ++nt)
            #pragma unroll
            for (int r = 0; r < 4; ++r) acc[mt][nt][r] = 0.f;

    // ---- prefetch first STAGES-1 tiles ----
    #pragma unroll
    for (int s = 0; s < STAGES - 1; ++s) {
        const int k0 = s * BK;
        const uint32_t so = (uint32_t)s * STAGE_B;
        cpa16(dA + so,      srcA + k0);
        cpa16(dA + so + 16, srcA + k0 + 4);
        cpa16(dB + so,      srcB + k0);
        cpa16(dB + so + 16, srcB + k0 + 4);
        asm volatile("cp.async.commit_group;");
    }

    for (int t = 0; t < NT_TILES; ++t) {
        asm volatile("cp.async.wait_group %0;" :: "n"(STAGES - 2));
        __syncthreads();

        if (t + STAGES - 1 < NT_TILES) {
            const int tp = t + STAGES - 1;
            const int k0 = tp * BK;
            const uint32_t so = (uint32_t)(tp & (STAGES - 1)) * STAGE_B;
            cpa16(dA + so,      srcA + k0);
            cpa16(dA + so + 16, srcA + k0 + 4);
            cpa16(dB + so,      srcB + k0);
            cpa16(dB + so + 16, srcB + k0 + 4);
        }
        asm volatile("cp.async.commit_group;");

        const float* As_s = smf + (t & (STAGES - 1)) * STAGE_W;
        const float* Bs_s = As_s + HALF_W;

        #pragma unroll
        for (int kk = 0; kk < BK; kk += 8) {
            float2 bf2[4];
            #pragma unroll
            for (int nt = 0; nt < 4; ++nt)
                bf2[nt] = *(const float2*)&Bs_s[(nW + nt * 8 + g) * ROWW + kk + 2 * tg];
            #pragma unroll
            for (int mt = 0; mt < 4; ++mt) {
                const int m = mW + mt * 16 + g;
                float2 alo = *(const float2*)&As_s[m * ROWW + kk + 2 * tg];
                float2 ahi = *(const float2*)&As_s[(m + 8) * ROWW + kk + 2 * tg];
                uint32_t afr[4];
                afr[0] = __float_as_uint(alo.x);
                afr[1] = __float_as_uint(ahi.x);
                afr[2] = __float_as_uint(alo.y);
                afr[3] = __float_as_uint(ahi.y);
                #pragma unroll
                for (int nt = 0; nt < 4; ++nt) {
                    uint32_t bfr[2];
                    bfr[0] = __float_as_uint(bf2[nt].x);
                    bfr[1] = __float_as_uint(bf2[nt].y);
                    mma_tf32(acc[mt][nt], afr, bfr);
                }
            }
        }
    }
    asm volatile("cp.async.wait_group 0;");

    // ---- epilogue: pure store (gproj added in LN) ----
    #pragma unroll
    for (int mt = 0; mt < 4; ++mt) {
        const int mBase = m0 + mW + mt * 16 + g;
        #pragma unroll
        for (int nt = 0; nt < 4; ++nt) {
            const int nl = nW + nt * 8 + tg * 2;
            float2 r0, r1;
            r0.x = acc[mt][nt][0];
            r0.y = acc[mt][nt][1];
            r1.x = acc[mt][nt][2];
            r1.y = acc[mt][nt][3];
            *(float2*)(out + (size_t)mBase * DD + n0 + nl)       = r0;
            *(float2*)(out + (size_t)(mBase + 8) * DD + n0 + nl) = r1;
        }
    }
}

// =====================================================================
// LayerNorm over last dim (768), fused +gproj; block 192, float4/thread
//   y[m] = LN(C[m] + gproj[m>>9]) * gamma + beta
// =====================================================================
__global__ __launch_bounds__(192)
void ln_kernel(float* __restrict__ y,
               const float* __restrict__ gamma,
               const float* __restrict__ beta)
{
    const int m = blockIdx.x;
    float4* row = (float4*)(y + (size_t)m * DD);
    const float4* gp = (const float4*)&g_gproj[m >> 9][0];
    const int t = threadIdx.x;

    float4 v = row[t];
    float4 a = gp[t];
    v.x += a.x; v.y += a.y; v.z += a.z; v.w += a.w;

    float s  = v.x + v.y + v.z + v.w;
    float s2 = v.x * v.x + v.y * v.y + v.z * v.z + v.w * v.w;
    #pragma unroll
    for (int o = 16; o; o >>= 1) {
        s  += __shfl_xor_sync(0xffffffffu, s,  o);
        s2 += __shfl_xor_sync(0xffffffffu, s2, o);
    }
    __shared__ float red[2][6];
    const int w = t >> 5, lane = t & 31;
    if (lane == 0) { red[0][w] = s; red[1][w] = s2; }
    __syncthreads();
    s = 0.f; s2 = 0.f;
    #pragma unroll
    for (int i = 0; i < 6; ++i) { s += red[0][i]; s2 += red[1][i]; }

    const float mean = s * (1.0f / DD);
    float var = s2 * (1.0f / DD) - mean * mean;
    var = fmaxf(var, 0.f);
    const float rstd = rsqrtf(var + LN_EPS);

    float4 ga = ((const float4*)gamma)[t];
    float4 be = ((const float4*)beta)[t];
    float4 o;
    o.x = (v.x - mean) * rstd * ga.x + be.x;
    o.y = (v.y - mean) * rstd * ga.y + be.y;
    o.z = (v.z - mean) * rstd * ga.z + be.z;
    o.w = (v.w - mean) * rstd * ga.w + be.w;
    row[t] = o;
}

// =====================================================================
// launch — graph chain (memory-bound) overlaps the compute-bound GEMM
// =====================================================================
extern "C" void kernel_launch(void* const* d_in, const int* in_sizes, int n_in,
                              void* d_out, int out_size)
{
    const int*   input_ids = (const int*)  d_in[0];
    const float* adj_cooc  = (const float*)d_in[1];
    const int*   gv_cooc   = (const int*)  d_in[2];
    const float* adj_het   = (const float*)d_in[3];
    const int*   gv_het    = (const int*)  d_in[4];
    const float* adj_isg   = (const float*)d_in[5];
    const int*   gv_isg    = (const int*)  d_in[6];
    const float* word_emb  = (const float*)d_in[7];
    const float* pos_emb   = (const float*)d_in[8];
    const float* W_cooc    = (const float*)d_in[9];
    const float* b_cooc    = (const float*)d_in[10];
    const float* W_het     = (const float*)d_in[11];
    const float* b_het     = (const float*)d_in[12];
    const float* W_isg     = (const float*)d_in[13];
    const float* b_isg     = (const float*)d_in[14];
    const float* W_proj    = (const float*)d_in[15];
    const float* b_proj    = (const float*)d_in[16];
    const float* ln_gamma  = (const float*)d_in[17];
    const float* ln_beta   = (const float*)d_in[18];
    float* out = (float*)d_out;

    cudaFuncSetAttribute(gemm_async_kernel,
                         cudaFuncAttributeMaxDynamicSharedMemorySize, GEMM_SMEM);

    // fork a side stream carrying the whole graph chain; the main stream
    // runs pack -> cvt -> GEMM.  The GEMM is compute-bound (DRAM ~3%), so
    // the memory-bound chain hides underneath it.  Join before LN, which
    // consumes both (adds gproj, then normalizes).
    cudaStream_t s1;
    cudaStreamCreateWithFlags(&s1, cudaStreamNonBlocking);
    cudaEvent_t e0, e1;
    cudaEventCreateWithFlags(&e0, cudaEventDisableTiming);
    cudaEventCreateWithFlags(&e1, cudaEventDisableTiming);

    cudaEventRecord(e0, 0);
    cudaStreamWaitEvent(s1, e0, 0);
    colsum_kernel<<<dim3(BB, 3, 4), 256, 0, s1>>>(adj_cooc, adj_het, adj_isg);
    gvec_part_kernel<<<dim3(BB, 3, 4), 768, 0, s1>>>(word_emb, gv_cooc, gv_het, gv_isg);
    gvec_fc_kernel<<<dim3(BB, 3), 768, 0, s1>>>(W_cooc, W_het, W_isg,
                                                b_cooc, b_het, b_isg);
    gproj_kernel<<<BB, 768, 0, s1>>>(W_proj, b_proj);
    cudaEventRecord(e1, s1);

    // main stream: operand prep then the big GEMM
    pack_kernel<<<M_TOT / 4, 384>>>(input_ids, word_emb, pos_emb);
    cvt_wp_kernel<<<DD / 4, 384>>>(W_proj);
    gemm_async_kernel<<<dim3(DD / BN, M_TOT / BM), 256, GEMM_SMEM>>>(out);

    // join, then fused gproj+LN
    cudaStreamWaitEvent(0, e1, 0);
    ln_kernel<<<M_TOT, 192>>>(out, ln_gamma, ln_beta);

    // NOTE: s1/e0/e1 intentionally not destroyed — destroying objects used
    // by an active capture invalidates the capture; host-side leak is
    // bounded (kernel_launch runs a handful of times).
}